// round 1
// baseline (speedup 1.0000x reference)
#include <cuda_runtime.h>
#include <math.h>

#define NN 25000
#define EE 400000

// ---------------- device scratch (no allocs allowed) ----------------
__device__ int   g_deg[NN];
__device__ int   g_rowptr[NN + 1];
__device__ int   g_cursor[NN];
__device__ int   g_ssrc[EE];
__device__ float g_Wtop[256 * 256];
__device__ float g_Wbot[256 * 256];
__device__ float g_u[NN * 256];
__device__ float g_v[NN * 256];
__device__ float g_agg[NN * 1024];
__device__ float g_alpha[NN];
__device__ float g_beta[NN];
__device__ float g_post[NN * 256];
__device__ float g_lin[NN * 256];
__device__ float g_h[NN * 256];
__device__ float g_bnsum[256];
__device__ float g_bnsq[256];

// ---------------- small utility kernels ----------------
__global__ void k_zero_int(int* p, int n) {
    int i = blockIdx.x * blockDim.x + threadIdx.x;
    if (i < n) p[i] = 0;
}
__global__ void k_zero_f(float* p, int n) {
    int i = blockIdx.x * blockDim.x + threadIdx.x;
    if (i < n) p[i] = 0.f;
}

__global__ void k_hist(const int* __restrict__ eidx) {
    int e = blockIdx.x * blockDim.x + threadIdx.x;
    if (e < EE) atomicAdd(&g_deg[eidx[EE + e]], 1);
}

// single-block exclusive scan over g_deg -> g_rowptr, g_cursor
__global__ void k_scan() {
    __shared__ int part[1024];
    const int CH = (NN + 1023) / 1024;  // 25
    int t = threadIdx.x;
    int base = t * CH;
    int s = 0;
    for (int i = 0; i < CH; i++) {
        int idx = base + i;
        if (idx < NN) s += g_deg[idx];
    }
    part[t] = s;
    __syncthreads();
    for (int off = 1; off < 1024; off <<= 1) {
        int v = 0;
        if (t >= off) v = part[t - off];
        __syncthreads();
        part[t] += v;
        __syncthreads();
    }
    int run = (t == 0) ? 0 : part[t - 1];
    for (int i = 0; i < CH; i++) {
        int idx = base + i;
        if (idx < NN) {
            g_rowptr[idx] = run;
            g_cursor[idx] = run;
            run += g_deg[idx];
        }
    }
    if (t == 1023) g_rowptr[NN] = EE;
}

__global__ void k_scatter(const int* __restrict__ eidx) {
    int e = blockIdx.x * blockDim.x + threadIdx.x;
    if (e < EE) {
        int tgt = eidx[EE + e];
        int pos = atomicAdd(&g_cursor[tgt], 1);
        g_ssrc[pos] = eidx[e];  // src
    }
}

// repack pre_W [T, 2*Fin, F] into Wtop/Wbot [Fin, T*F]
__global__ void k_repack(const float* __restrict__ preW, float* __restrict__ Wtop,
                         float* __restrict__ Wbot, int Fin, int F) {
    int i = blockIdx.x * blockDim.x + threadIdx.x;
    int total = 4 * Fin * F;
    if (i < total) {
        int f = i % F;
        int c = (i / F) % Fin;
        int t = i / (F * Fin);
        int C = 4 * F;
        Wtop[c * C + t * F + f] = preW[(t * 2 * Fin + c) * F + f];
        Wbot[c * C + t * F + f] = preW[(t * 2 * Fin + Fin + c) * F + f];
    }
}

// ---------------- generic tiled fp32 GEMM: C = A[M,K] @ B[K,Nc] (+bias) ----------------
// 64x64 tile, BK=16, 256 threads, 4x4 per thread. Nc % 64 == 0, K % 16 == 0.
__global__ void k_gemm(const float* __restrict__ A, const float* __restrict__ B,
                       const float* __restrict__ bias, float* __restrict__ C,
                       int M, int K, int Nc) {
    __shared__ float sA[16][64];
    __shared__ float sB[16][64];
    int bm = blockIdx.y * 64, bn = blockIdx.x * 64;
    int tid = threadIdx.x;
    int tx = tid & 15, ty = tid >> 4;
    float acc[4][4] = {};
    for (int k0 = 0; k0 < K; k0 += 16) {
        for (int i = tid; i < 1024; i += 256) {
            int r = i >> 4, kk = i & 15;
            int row = bm + r;
            sA[kk][r] = (row < M) ? A[(size_t)row * K + k0 + kk] : 0.f;
        }
        for (int i = tid; i < 1024; i += 256) {
            int kk = i >> 6, c = i & 63;
            sB[kk][c] = B[(size_t)(k0 + kk) * Nc + bn + c];
        }
        __syncthreads();
#pragma unroll
        for (int kk = 0; kk < 16; kk++) {
            float a[4], b[4];
#pragma unroll
            for (int i = 0; i < 4; i++) a[i] = sA[kk][ty * 4 + i];
#pragma unroll
            for (int j = 0; j < 4; j++) b[j] = sB[kk][tx * 4 + j];
#pragma unroll
            for (int i = 0; i < 4; i++)
#pragma unroll
                for (int j = 0; j < 4; j++) acc[i][j] += a[i] * b[j];
        }
        __syncthreads();
    }
#pragma unroll
    for (int i = 0; i < 4; i++) {
        int row = bm + ty * 4 + i;
        if (row < M) {
#pragma unroll
            for (int j = 0; j < 4; j++) {
                int c = bn + tx * 4 + j;
                float v = acc[i][j];
                if (bias) v += bias[c];
                C[(size_t)row * Nc + c] = v;
            }
        }
    }
}

// ---------------- segment reduce: per node, over CSR-sorted src list ----------------
// msg_e = u[tgt] + v[src]. Computes mean/min/max/std + per-node scalers.
// C = T*F total columns. agg layout [N, T, 4F] = [mean|min|max|std] per tower.
template <int C, int F>
__global__ void k_segreduce(const float* __restrict__ u, const float* __restrict__ v,
                            float* __restrict__ agg, float* __restrict__ alpha,
                            float* __restrict__ beta, const float* __restrict__ avg_log) {
    int n = blockIdx.x;
    int j = threadIdx.x;
    int beg = g_rowptr[n], end = g_rowptr[n + 1];
    float s = 0.f, s2 = 0.f, mn = 3.4e38f, mx = -3.4e38f;
    for (int e = beg; e < end; e++) {
        int sidx = g_ssrc[e];
        float val = v[(size_t)sidx * C + j];
        s += val;
        s2 += val * val;
        mn = fminf(mn, val);
        mx = fmaxf(mx, val);
    }
    int deg = end - beg;
    float uu = u[(size_t)n * C + j];
    float degf = (float)deg;
    float degc = fmaxf(degf, 1.f);
    float mean = (deg > 0) ? (uu + s / degf) : 0.f;
    float s2f = degf * uu * uu + 2.f * uu * s + s2;
    float var = fmaxf(s2f / degc - mean * mean, 0.f);
    float sd = sqrtf(var + 1e-5f);
    float mnv = (deg > 0) ? (uu + mn) : 0.f;
    float mxv = (deg > 0) ? (uu + mx) : 0.f;
    int t = j / F, f = j % F;
    float* base = agg + (size_t)n * (4 * C) + t * (4 * F);
    base[f] = mean;
    base[F + f] = mnv;
    base[2 * F + f] = mxv;
    base[3 * F + f] = sd;
    if (j == 0) {
        float dl = logf(degc + 1.f);
        alpha[n] = dl / avg_log[0];
        beta[n] = avg_log[0] / dl;
    }
}

// ---------------- fused post-MLP GEMM ----------------
// post_in = [x (FIN) | agg (4F) | alpha*agg (4F) | beta*agg (4F)] per tower.
// out[n, t*F+f] = acc1 + alpha[n]*acc2 + beta[n]*acc3 + PB[t*F+f]
// where acc1 = x@Wx + agg@W1, acc2 = agg@W2, acc3 = agg@W3.
template <int FIN, int F>
__global__ void k_post(const float* __restrict__ X, const float* __restrict__ AGG,
                       const float* __restrict__ PW, const float* __restrict__ PB,
                       const float* __restrict__ alpha, const float* __restrict__ beta,
                       float* __restrict__ OUT, int M) {
    constexpr int C4 = 4 * F;        // agg cols per tower
    constexpr int KW = FIN + 12 * F; // weight rows per tower
    constexpr int TX = F / 4;
    constexpr int TY = 256 / TX;
    constexpr int RPT = 64 / TY;
    constexpr int AGGSTRIDE = 16 * F;  // T*4F
    int t = blockIdx.x;
    int bm = blockIdx.y * 64;
    __shared__ float sA[16][64];
    __shared__ float sW[3][16][F];
    int tid = threadIdx.x;
    int tx = tid % TX, ty = tid / TX;
    float a1[RPT][4] = {}, a2[RPT][4] = {}, a3[RPT][4] = {};
    const float* Wt = PW + (size_t)t * KW * F;

    // x section -> acc1 only
    for (int k0 = 0; k0 < FIN; k0 += 16) {
        for (int i = tid; i < 1024; i += 256) {
            int r = i >> 4, kk = i & 15;
            int row = bm + r;
            sA[kk][r] = (row < M) ? X[(size_t)row * FIN + k0 + kk] : 0.f;
        }
        for (int i = tid; i < 16 * F; i += 256) {
            int kk = i / F, f = i % F;
            sW[0][kk][f] = Wt[(size_t)(k0 + kk) * F + f];
        }
        __syncthreads();
#pragma unroll
        for (int kk = 0; kk < 16; kk++) {
            float a[RPT], w[4];
#pragma unroll
            for (int i = 0; i < RPT; i++) a[i] = sA[kk][ty * RPT + i];
#pragma unroll
            for (int j = 0; j < 4; j++) w[j] = sW[0][kk][tx * 4 + j];
#pragma unroll
            for (int i = 0; i < RPT; i++)
#pragma unroll
                for (int j = 0; j < 4; j++) a1[i][j] += a[i] * w[j];
        }
        __syncthreads();
    }
    // agg section -> acc1/acc2/acc3
    for (int k0 = 0; k0 < C4; k0 += 16) {
        for (int i = tid; i < 1024; i += 256) {
            int r = i >> 4, kk = i & 15;
            int row = bm + r;
            sA[kk][r] = (row < M) ? AGG[(size_t)row * AGGSTRIDE + t * C4 + k0 + kk] : 0.f;
        }
        for (int i = tid; i < 16 * F; i += 256) {
            int kk = i / F, f = i % F;
            sW[0][kk][f] = Wt[(size_t)(FIN + k0 + kk) * F + f];
            sW[1][kk][f] = Wt[(size_t)(FIN + C4 + k0 + kk) * F + f];
            sW[2][kk][f] = Wt[(size_t)(FIN + 2 * C4 + k0 + kk) * F + f];
        }
        __syncthreads();
#pragma unroll
        for (int kk = 0; kk < 16; kk++) {
            float a[RPT], w1[4], w2[4], w3[4];
#pragma unroll
            for (int i = 0; i < RPT; i++) a[i] = sA[kk][ty * RPT + i];
#pragma unroll
            for (int j = 0; j < 4; j++) {
                w1[j] = sW[0][kk][tx * 4 + j];
                w2[j] = sW[1][kk][tx * 4 + j];
                w3[j] = sW[2][kk][tx * 4 + j];
            }
#pragma unroll
            for (int i = 0; i < RPT; i++)
#pragma unroll
                for (int j = 0; j < 4; j++) {
                    a1[i][j] += a[i] * w1[j];
                    a2[i][j] += a[i] * w2[j];
                    a3[i][j] += a[i] * w3[j];
                }
        }
        __syncthreads();
    }
    // epilogue
#pragma unroll
    for (int i = 0; i < RPT; i++) {
        int row = bm + ty * RPT + i;
        if (row < M) {
            float al = alpha[row], be = beta[row];
#pragma unroll
            for (int j = 0; j < 4; j++) {
                int f = tx * 4 + j;
                float v = a1[i][j] + al * a2[i][j] + be * a3[i][j] + PB[t * F + f];
                OUT[(size_t)row * (4 * F) + t * F + f] = v;
            }
        }
    }
}

// ---------------- batchnorm ----------------
__global__ void k_bnstats(const float* __restrict__ Y, float* __restrict__ sum,
                          float* __restrict__ sq, int M, int C) {
    int j = threadIdx.x;
    if (j >= C) return;
    float s = 0.f, q = 0.f;
    for (int r = blockIdx.x; r < M; r += gridDim.x) {
        float v = Y[(size_t)r * C + j];
        if (!isfinite(v)) v = 0.f;
        s += v;
        q += v * v;
    }
    atomicAdd(&sum[j], s);
    atomicAdd(&sq[j], q);
}

__global__ void k_bnapply(const float* __restrict__ Y, const float* __restrict__ sum,
                          const float* __restrict__ sq, const float* __restrict__ g,
                          const float* __restrict__ b, float* __restrict__ OUT, int M, int C) {
    int idx = blockIdx.x * blockDim.x + threadIdx.x;
    if (idx < M * C) {
        int j = idx % C;
        float m = sum[j] / (float)M;
        float var = sq[j] / (float)M - m * m;
        float inv = rsqrtf(var + 1e-5f);
        float y = Y[idx];
        if (!isfinite(y)) y = 0.f;
        OUT[idx] = fmaxf(0.f, g[j] * (y - m) * inv + b[j]);
    }
}

// ---------------- launch ----------------
extern "C" void kernel_launch(void* const* d_in, const int* in_sizes, int n_in,
                              void* d_out, int out_size) {
    const float* x       = (const float*)d_in[0];
    const int*   eidx    = (const int*)d_in[1];
    const float* avg_log = (const float*)d_in[2];
    const float* pre1W   = (const float*)d_in[3];
    const float* pre1b   = (const float*)d_in[4];
    const float* post1W  = (const float*)d_in[5];
    const float* post1b  = (const float*)d_in[6];
    const float* lin1W   = (const float*)d_in[7];
    const float* lin1b   = (const float*)d_in[8];
    const float* bn1g    = (const float*)d_in[9];
    const float* bn1b    = (const float*)d_in[10];
    const float* pre2W   = (const float*)d_in[11];
    const float* pre2b   = (const float*)d_in[12];
    const float* post2W  = (const float*)d_in[13];
    const float* post2b  = (const float*)d_in[14];
    const float* lin2W   = (const float*)d_in[15];
    const float* lin2b   = (const float*)d_in[16];
    const float* bn2g    = (const float*)d_in[17];
    const float* bn2b    = (const float*)d_in[18];

    int *deg, *Wdummy;
    (void)Wdummy;
    float *Wtop, *Wbot, *u, *v, *agg, *alpha, *beta, *post, *lin, *h, *bnsum, *bnsq;
    cudaGetSymbolAddress((void**)&deg, g_deg);
    cudaGetSymbolAddress((void**)&Wtop, g_Wtop);
    cudaGetSymbolAddress((void**)&Wbot, g_Wbot);
    cudaGetSymbolAddress((void**)&u, g_u);
    cudaGetSymbolAddress((void**)&v, g_v);
    cudaGetSymbolAddress((void**)&agg, g_agg);
    cudaGetSymbolAddress((void**)&alpha, g_alpha);
    cudaGetSymbolAddress((void**)&beta, g_beta);
    cudaGetSymbolAddress((void**)&post, g_post);
    cudaGetSymbolAddress((void**)&lin, g_lin);
    cudaGetSymbolAddress((void**)&h, g_h);
    cudaGetSymbolAddress((void**)&bnsum, g_bnsum);
    cudaGetSymbolAddress((void**)&bnsq, g_bnsq);

    // ---- CSR build ----
    k_zero_int<<<(NN + 255) / 256, 256>>>(deg, NN);
    k_hist<<<(EE + 255) / 256, 256>>>(eidx);
    k_scan<<<1, 1024>>>();
    k_scatter<<<(EE + 255) / 256, 256>>>(eidx);

    int mblocks = (NN + 63) / 64;  // 391

    // ---- layer 1 (Fin=128, T=4, F=64, C=256) ----
    k_repack<<<(4 * 128 * 64 + 255) / 256, 256>>>(pre1W, Wtop, Wbot, 128, 64);
    {
        dim3 g(4, mblocks);
        k_gemm<<<g, 256>>>(x, Wtop, pre1b, u, NN, 128, 256);
        k_gemm<<<g, 256>>>(x, Wbot, nullptr, v, NN, 128, 256);
    }
    k_segreduce<256, 64><<<NN, 256>>>(u, v, agg, alpha, beta, avg_log);
    {
        dim3 g(4, mblocks);
        k_post<128, 64><<<g, 256>>>(x, agg, post1W, post1b, alpha, beta, post, NN);
        k_gemm<<<g, 256>>>(post, lin1W, lin1b, lin, NN, 256, 256);
    }
    k_zero_f<<<1, 256>>>(bnsum, 256);
    k_zero_f<<<1, 256>>>(bnsq, 256);
    k_bnstats<<<512, 256>>>(lin, bnsum, bnsq, NN, 256);
    k_bnapply<<<(NN * 256 + 255) / 256, 256>>>(lin, bnsum, bnsq, bn1g, bn1b, h, NN, 256);

    // ---- layer 2 (Fin=256, T=4, F=32, C=128) ----
    k_repack<<<(4 * 256 * 32 + 255) / 256, 256>>>(pre2W, Wtop, Wbot, 256, 32);
    {
        dim3 g(2, mblocks);
        k_gemm<<<g, 256>>>(h, Wtop, pre2b, u, NN, 256, 128);
        k_gemm<<<g, 256>>>(h, Wbot, nullptr, v, NN, 256, 128);
    }
    k_segreduce<128, 32><<<NN, 128>>>(u, v, agg, alpha, beta, avg_log);
    {
        dim3 g(4, mblocks);
        k_post<256, 32><<<g, 256>>>(h, agg, post2W, post2b, alpha, beta, post, NN);
    }
    {
        dim3 g(2, mblocks);
        k_gemm<<<g, 256>>>(post, lin2W, lin2b, lin, NN, 128, 128);
    }
    k_zero_f<<<1, 256>>>(bnsum, 256);
    k_zero_f<<<1, 256>>>(bnsq, 256);
    k_bnstats<<<512, 128>>>(lin, bnsum, bnsq, NN, 128);
    k_bnapply<<<(NN * 128 + 255) / 256, 256>>>(lin, bnsum, bnsq, bn2g, bn2b,
                                               (float*)d_out, NN, 128);
}

// round 3
// speedup vs baseline: 1.8180x; 1.8180x over previous
#include <cuda_runtime.h>
#include <cuda_bf16.h>
#include <math.h>
#include <stdint.h>

#define NN 25000
#define EE 400000

// ---------------- device scratch ----------------
__device__ int   g_deg[NN];
__device__ int   g_rowptr[NN + 1];
__device__ int   g_cursor[NN];
__device__ int   g_ssrc[EE];
__device__ float g_u[NN * 256];
__device__ float g_v[NN * 256];
__device__ float g_agg[NN * 1024];
__device__ float g_alpha[NN];
__device__ float g_beta[NN];
__device__ float g_px[NN * 256];
__device__ float g_pc[NN * 768];
__device__ float g_post[NN * 256];
__device__ float g_lin[NN * 256];
__device__ float g_h[NN * 256];
__device__ float g_bnsum[256];
__device__ float g_bnsq[256];

// bf16 weight pool (hi / lo split), element offsets:
#define OFF_TOP 0
#define OFF_BOT 65536
#define OFF_X   131072
#define OFF_CAT 196608
#define OFF_LIN 393216
#define POOL    458752
__device__ __nv_bfloat16 g_bhi[POOL];
__device__ __nv_bfloat16 g_blo[POOL];

__device__ __forceinline__ uint32_t s2u(const void* p) {
    return (uint32_t)__cvta_generic_to_shared(p);
}

// ---------------- CSR build ----------------
__global__ void k_zero_int(int* p, int n) {
    int i = blockIdx.x * blockDim.x + threadIdx.x;
    if (i < n) p[i] = 0;
}
__global__ void k_zero_f(float* p, int n) {
    int i = blockIdx.x * blockDim.x + threadIdx.x;
    if (i < n) p[i] = 0.f;
}
__global__ void k_hist(const int* __restrict__ eidx) {
    int e = blockIdx.x * blockDim.x + threadIdx.x;
    if (e < EE) atomicAdd(&g_deg[eidx[EE + e]], 1);
}
__global__ void k_scan() {
    __shared__ int part[1024];
    const int CH = (NN + 1023) / 1024;
    int t = threadIdx.x;
    int base = t * CH;
    int s = 0;
    for (int i = 0; i < CH; i++) {
        int idx = base + i;
        if (idx < NN) s += g_deg[idx];
    }
    part[t] = s;
    __syncthreads();
    for (int off = 1; off < 1024; off <<= 1) {
        int v = 0;
        if (t >= off) v = part[t - off];
        __syncthreads();
        part[t] += v;
        __syncthreads();
    }
    int run = (t == 0) ? 0 : part[t - 1];
    for (int i = 0; i < CH; i++) {
        int idx = base + i;
        if (idx < NN) {
            g_rowptr[idx] = run;
            g_cursor[idx] = run;
            run += g_deg[idx];
        }
    }
    if (t == 1023) g_rowptr[NN] = EE;
}
__global__ void k_scatter(const int* __restrict__ eidx) {
    int e = blockIdx.x * blockDim.x + threadIdx.x;
    if (e < EE) {
        int tgt = eidx[EE + e];
        int pos = atomicAdd(&g_cursor[tgt], 1);
        g_ssrc[pos] = eidx[e];
    }
}

// ---------------- weight prep: transpose to [N,K] + bf16 hi/lo split ----------------
__device__ __forceinline__ void put_w(float w, int out_idx) {
    __nv_bfloat16 h = __float2bfloat16(w);
    g_bhi[out_idx] = h;
    g_blo[out_idx] = __float2bfloat16(w - __bfloat162float(h));
}
__global__ void k_prep(const float* __restrict__ preW, const float* __restrict__ postW,
                       const float* __restrict__ linW, int Fin, int F, int linN, int linK) {
    int TF = 4 * F;
    int KW = Fin + 12 * F;
    int s0 = TF * Fin;
    int s1 = TF * Fin;
    int s2 = 4 * (3 * F) * (4 * F);
    int s3 = linN * linK;
    int total = s0 + s1 + s2 + s3;
    for (int i = blockIdx.x * blockDim.x + threadIdx.x; i < total; i += gridDim.x * blockDim.x) {
        if (i < s0) {
            int n = i / Fin, k = i % Fin;
            int t = n / F, f = n % F;
            put_w(preW[(t * 2 * Fin + k) * F + f], OFF_TOP + n * Fin + k);
            put_w(preW[(t * 2 * Fin + Fin + k) * F + f], OFF_BOT + n * Fin + k);
        } else if (i < s0 + s1) {
            int j = i - s0;
            int n = j / Fin, k = j % Fin;
            int t = n / F, f = n % F;
            put_w(postW[(t * KW + k) * F + f], OFF_X + n * Fin + k);
        } else if (i < s0 + s1 + s2) {
            int j = i - s0 - s1;
            int per = (3 * F) * (4 * F);
            int t = j / per;
            int r = j % per;
            int n2 = r / (4 * F), k = r % (4 * F);
            int blk = n2 / F, f = n2 % F;
            int row = Fin + blk * 4 * F + k;
            put_w(postW[(t * KW + row) * F + f], OFF_CAT + (t * 3 * F + n2) * (4 * F) + k);
        } else {
            int j = i - s0 - s1 - s2;
            int n = j / linK, k = j % linK;
            put_w(linW[k * linN + n], OFF_LIN + n * linK + k);
        }
    }
}

// ---------------- mma.sync helpers ----------------
#define LDMX4(r, addr)                                                              \
    asm volatile("ldmatrix.sync.aligned.m8n8.x4.shared.b16 {%0,%1,%2,%3}, [%4];"    \
                 : "=r"((r)[0]), "=r"((r)[1]), "=r"((r)[2]), "=r"((r)[3])           \
                 : "r"(addr))

__device__ __forceinline__ void mma16816(float* c, const uint32_t* a, const uint32_t* b) {
    asm volatile(
        "mma.sync.aligned.m16n8k16.row.col.f32.bf16.bf16.f32 "
        "{%0,%1,%2,%3}, {%4,%5,%6,%7}, {%8,%9}, {%0,%1,%2,%3};"
        : "+f"(c[0]), "+f"(c[1]), "+f"(c[2]), "+f"(c[3])
        : "r"(a[0]), "r"(a[1]), "r"(a[2]), "r"(a[3]), "r"(b[0]), "r"(b[1]));
}

__device__ __forceinline__ uint32_t pack_bf2(float a, float b) {
    __nv_bfloat162 t = __floats2bfloat162_rn(a, b);
    return *(uint32_t*)&t;
}

// ---------------- warp-MMA bf16x3 GEMM ----------------
// C[row, coff + z*cz + n] = sum_k A[row*lda + aoff + z*az + k] * B[z][n, k] (+bias[n])
// B: bf16 hi/lo [Ntot, K] row-major.  Tile: 128M x 64N x 32K, 8 warps.
__global__ __launch_bounds__(256, 2) void k_wmma(
    const float* __restrict__ A, int lda, int aoff, int az,
    const __nv_bfloat16* __restrict__ Bhi, const __nv_bfloat16* __restrict__ Blo, int bz,
    const float* __restrict__ bias, float* __restrict__ C, int ldc, int coff, int cz,
    int M, int K, int Ntot) {
    __shared__ __nv_bfloat16 sAh[128][40];
    __shared__ __nv_bfloat16 sAl[128][40];
    __shared__ __nv_bfloat16 sBh[64][40];
    __shared__ __nv_bfloat16 sBl[64][40];

    int tid = threadIdx.x;
    int w = tid >> 5, lane = tid & 31;
    int wm = w & 3, wn = w >> 2;
    int bm = blockIdx.x * 128;
    int bn = blockIdx.y * 64;
    int z = blockIdx.z;

    const float* Ab = A + (size_t)aoff + (size_t)z * az;
    const __nv_bfloat16* Bh0 = Bhi + (size_t)z * bz;
    const __nv_bfloat16* Bl0 = Blo + (size_t)z * bz;

    float acc[2][4][4] = {};

    for (int k0 = 0; k0 < K; k0 += 32) {
        // ---- load A chunk: 128x32 fp32 -> hi/lo bf16 ----
        for (int i = tid; i < 1024; i += 256) {
            int row = i >> 3, c4 = (i & 7) << 2;
            float4 v = make_float4(0.f, 0.f, 0.f, 0.f);
            int rg = bm + row;
            if (rg < M) v = *(const float4*)(Ab + (size_t)rg * lda + k0 + c4);
            __nv_bfloat16 hx = __float2bfloat16(v.x), hy = __float2bfloat16(v.y);
            __nv_bfloat16 hz = __float2bfloat16(v.z), hw = __float2bfloat16(v.w);
            __nv_bfloat162 h01; h01.x = hx; h01.y = hy;
            __nv_bfloat162 h23; h23.x = hz; h23.y = hw;
            uint2 hh = make_uint2(*(uint32_t*)&h01, *(uint32_t*)&h23);
            uint2 ll = make_uint2(pack_bf2(v.x - __bfloat162float(hx), v.y - __bfloat162float(hy)),
                                  pack_bf2(v.z - __bfloat162float(hz), v.w - __bfloat162float(hw)));
            *(uint2*)&sAh[row][c4] = hh;
            *(uint2*)&sAl[row][c4] = ll;
        }
        // ---- load B chunk: 64x32 bf16 hi/lo ----
        {
            int row = tid >> 2, q = tid & 3;
            int n = bn + row;
            uint4 vh = make_uint4(0, 0, 0, 0), vl = make_uint4(0, 0, 0, 0);
            if (n < Ntot) {
                vh = *(const uint4*)(Bh0 + (size_t)n * K + k0 + q * 8);
                vl = *(const uint4*)(Bl0 + (size_t)n * K + k0 + q * 8);
            }
            *(uint4*)&sBh[row][q * 8] = vh;
            *(uint4*)&sBl[row][q * 8] = vl;
        }
        __syncthreads();

        // ---- compute ----
#pragma unroll
        for (int ks = 0; ks < 2; ks++) {
            uint32_t ah[2][4], al[2][4], bh[4][2], bl[4][2];
#pragma unroll
            for (int mi = 0; mi < 2; mi++) {
                int r = wm * 32 + mi * 16 + (lane & 15);
                int kk = ks * 16 + ((lane >> 4) << 3);
                LDMX4(ah[mi], s2u(&sAh[r][kk]));
                LDMX4(al[mi], s2u(&sAl[r][kk]));
            }
#pragma unroll
            for (int np = 0; np < 2; np++) {
                int rr = wn * 32 + np * 16 + (lane & 7) + ((lane & 16) ? 8 : 0);
                int kk = ks * 16 + ((lane & 8) ? 8 : 0);
                uint32_t t[4];
                LDMX4(t, s2u(&sBh[rr][kk]));
                bh[np * 2][0] = t[0]; bh[np * 2][1] = t[1];
                bh[np * 2 + 1][0] = t[2]; bh[np * 2 + 1][1] = t[3];
                LDMX4(t, s2u(&sBl[rr][kk]));
                bl[np * 2][0] = t[0]; bl[np * 2][1] = t[1];
                bl[np * 2 + 1][0] = t[2]; bl[np * 2 + 1][1] = t[3];
            }
#pragma unroll
            for (int mi = 0; mi < 2; mi++)
#pragma unroll
                for (int ni = 0; ni < 4; ni++) {
                    mma16816(acc[mi][ni], ah[mi], bh[ni]);
                    mma16816(acc[mi][ni], ah[mi], bl[ni]);
                    mma16816(acc[mi][ni], al[mi], bh[ni]);
                }
        }
        __syncthreads();
    }

    // ---- epilogue ----
#pragma unroll
    for (int mi = 0; mi < 2; mi++) {
#pragma unroll
        for (int ni = 0; ni < 4; ni++) {
            int col = bn + wn * 32 + ni * 8 + 2 * (lane & 3);
            if (col >= Ntot) continue;
            float bv0 = bias ? bias[col] : 0.f;
            float bv1 = bias ? bias[col + 1] : 0.f;
            int r0 = bm + wm * 32 + mi * 16 + (lane >> 2);
            size_t cb = (size_t)coff + (size_t)z * cz + col;
            if (r0 < M) {
                float2 o = make_float2(acc[mi][ni][0] + bv0, acc[mi][ni][1] + bv1);
                *(float2*)(C + (size_t)r0 * ldc + cb) = o;
            }
            if (r0 + 8 < M) {
                float2 o = make_float2(acc[mi][ni][2] + bv0, acc[mi][ni][3] + bv1);
                *(float2*)(C + (size_t)(r0 + 8) * ldc + cb) = o;
            }
        }
    }
}

// ---------------- segment reduce ----------------
template <int C, int F>
__global__ void k_segreduce(const float* __restrict__ u, const float* __restrict__ v,
                            float* __restrict__ agg, float* __restrict__ alpha,
                            float* __restrict__ beta, const float* __restrict__ avg_log) {
    int n = blockIdx.x;
    int j = threadIdx.x;
    int beg = g_rowptr[n], end = g_rowptr[n + 1];
    float s = 0.f, s2 = 0.f, mn = 3.4e38f, mx = -3.4e38f;
    for (int e = beg; e < end; e++) {
        int sidx = g_ssrc[e];
        float val = v[(size_t)sidx * C + j];
        s += val;
        s2 += val * val;
        mn = fminf(mn, val);
        mx = fmaxf(mx, val);
    }
    int deg = end - beg;
    float uu = u[(size_t)n * C + j];
    float degf = (float)deg;
    float degc = fmaxf(degf, 1.f);
    float mean = (deg > 0) ? (uu + s / degf) : 0.f;
    float s2f = degf * uu * uu + 2.f * uu * s + s2;
    float var = fmaxf(s2f / degc - mean * mean, 0.f);
    float sd = sqrtf(var + 1e-5f);
    float mnv = (deg > 0) ? (uu + mn) : 0.f;
    float mxv = (deg > 0) ? (uu + mx) : 0.f;
    int t = j / F, f = j % F;
    float* base = agg + (size_t)n * (4 * C) + t * (4 * F);
    base[f] = mean;
    base[F + f] = mnv;
    base[2 * F + f] = mxv;
    base[3 * F + f] = sd;
    if (j == 0) {
        float dl = logf(degc + 1.f);
        alpha[n] = dl / avg_log[0];
        beta[n] = avg_log[0] / dl;
    }
}

// ---------------- combine: post = px + pc1 + a*pc2 + b*pc3 ----------------
__global__ void k_combine(const float* __restrict__ px, const float* __restrict__ pc,
                          const float* __restrict__ alpha, const float* __restrict__ beta,
                          float* __restrict__ out, int C, int F, int ldpc) {
    int idx = blockIdx.x * blockDim.x + threadIdx.x;
    if (idx < NN * C) {
        int n = idx / C, c = idx % C;
        int t = c / F, f = c % F;
        const float* p = pc + (size_t)n * ldpc + t * 3 * F;
        out[idx] = px[idx] + p[f] + alpha[n] * p[F + f] + beta[n] * p[2 * F + f];
    }
}

// ---------------- batchnorm ----------------
__global__ void k_bnstats(const float* __restrict__ Y, float* __restrict__ sum,
                          float* __restrict__ sq, int M, int C) {
    int j = threadIdx.x;
    if (j >= C) return;
    float s = 0.f, q = 0.f;
    for (int r = blockIdx.x; r < M; r += gridDim.x) {
        float v = Y[(size_t)r * C + j];
        if (!isfinite(v)) v = 0.f;
        s += v;
        q += v * v;
    }
    atomicAdd(&sum[j], s);
    atomicAdd(&sq[j], q);
}
__global__ void k_bnapply(const float* __restrict__ Y, const float* __restrict__ sum,
                          const float* __restrict__ sq, const float* __restrict__ g,
                          const float* __restrict__ b, float* __restrict__ OUT, int M, int C) {
    int idx = blockIdx.x * blockDim.x + threadIdx.x;
    if (idx < M * C) {
        int j = idx % C;
        float m = sum[j] / (float)M;
        float var = sq[j] / (float)M - m * m;
        float inv = rsqrtf(var + 1e-5f);
        float y = Y[idx];
        if (!isfinite(y)) y = 0.f;
        OUT[idx] = fmaxf(0.f, g[j] * (y - m) * inv + b[j]);
    }
}

// ---------------- launch ----------------
extern "C" void kernel_launch(void* const* d_in, const int* in_sizes, int n_in,
                              void* d_out, int out_size) {
    const float* x       = (const float*)d_in[0];
    const int*   eidx    = (const int*)d_in[1];
    const float* avg_log = (const float*)d_in[2];
    const float* pre1W   = (const float*)d_in[3];
    const float* pre1b   = (const float*)d_in[4];
    const float* post1W  = (const float*)d_in[5];
    const float* post1b  = (const float*)d_in[6];
    const float* lin1W   = (const float*)d_in[7];
    const float* lin1b   = (const float*)d_in[8];
    const float* bn1g    = (const float*)d_in[9];
    const float* bn1b    = (const float*)d_in[10];
    const float* pre2W   = (const float*)d_in[11];
    const float* pre2b   = (const float*)d_in[12];
    const float* post2W  = (const float*)d_in[13];
    const float* post2b  = (const float*)d_in[14];
    const float* lin2W   = (const float*)d_in[15];
    const float* lin2b   = (const float*)d_in[16];
    const float* bn2g    = (const float*)d_in[17];
    const float* bn2b    = (const float*)d_in[18];

    int* deg;
    float *u, *v, *agg, *alpha, *beta, *px, *pc, *post, *lin, *h, *bnsum, *bnsq;
    __nv_bfloat16 *bhi, *blo;
    cudaGetSymbolAddress((void**)&deg, g_deg);
    cudaGetSymbolAddress((void**)&u, g_u);
    cudaGetSymbolAddress((void**)&v, g_v);
    cudaGetSymbolAddress((void**)&agg, g_agg);
    cudaGetSymbolAddress((void**)&alpha, g_alpha);
    cudaGetSymbolAddress((void**)&beta, g_beta);
    cudaGetSymbolAddress((void**)&px, g_px);
    cudaGetSymbolAddress((void**)&pc, g_pc);
    cudaGetSymbolAddress((void**)&post, g_post);
    cudaGetSymbolAddress((void**)&lin, g_lin);
    cudaGetSymbolAddress((void**)&h, g_h);
    cudaGetSymbolAddress((void**)&bnsum, g_bnsum);
    cudaGetSymbolAddress((void**)&bnsq, g_bnsq);
    cudaGetSymbolAddress((void**)&bhi, g_bhi);
    cudaGetSymbolAddress((void**)&blo, g_blo);

    // ---- CSR build ----
    k_zero_int<<<(NN + 255) / 256, 256>>>(deg, NN);
    k_hist<<<(EE + 255) / 256, 256>>>(eidx);
    k_scan<<<1, 1024>>>();
    k_scatter<<<(EE + 255) / 256, 256>>>(eidx);

    const int mt = (NN + 127) / 128;  // 196

    // =================== layer 1 (Fin=128, F=64, TF=256) ===================
    k_prep<<<320, 256>>>(pre1W, post1W, lin1W, 128, 64, 256, 256);
    k_wmma<<<dim3(mt, 4, 1), 256>>>(x, 128, 0, 0, bhi + OFF_TOP, blo + OFF_TOP, 0,
                                    pre1b, u, 256, 0, 0, NN, 128, 256);
    k_wmma<<<dim3(mt, 4, 1), 256>>>(x, 128, 0, 0, bhi + OFF_BOT, blo + OFF_BOT, 0,
                                    nullptr, v, 256, 0, 0, NN, 128, 256);
    k_segreduce<256, 64><<<NN, 256>>>(u, v, agg, alpha, beta, avg_log);
    k_wmma<<<dim3(mt, 4, 1), 256>>>(x, 128, 0, 0, bhi + OFF_X, blo + OFF_X, 0,
                                    post1b, px, 256, 0, 0, NN, 128, 256);
    k_wmma<<<dim3(mt, 3, 4), 256>>>(agg, 1024, 0, 256, bhi + OFF_CAT, blo + OFF_CAT,
                                    192 * 256, nullptr, pc, 768, 0, 192, NN, 256, 192);
    k_combine<<<(NN * 256 + 255) / 256, 256>>>(px, pc, alpha, beta, post, 256, 64, 768);
    k_wmma<<<dim3(mt, 4, 1), 256>>>(post, 256, 0, 0, bhi + OFF_LIN, blo + OFF_LIN, 0,
                                    lin1b, lin, 256, 0, 0, NN, 256, 256);
    k_zero_f<<<1, 256>>>(bnsum, 256);
    k_zero_f<<<1, 256>>>(bnsq, 256);
    k_bnstats<<<512, 256>>>(lin, bnsum, bnsq, NN, 256);
    k_bnapply<<<(NN * 256 + 255) / 256, 256>>>(lin, bnsum, bnsq, bn1g, bn1b, h, NN, 256);

    // =================== layer 2 (Fin=256, F=32, TF=128) ===================
    k_prep<<<320, 256>>>(pre2W, post2W, lin2W, 256, 32, 128, 128);
    k_wmma<<<dim3(mt, 2, 1), 256>>>(h, 256, 0, 0, bhi + OFF_TOP, blo + OFF_TOP, 0,
                                    pre2b, u, 128, 0, 0, NN, 256, 128);
    k_wmma<<<dim3(mt, 2, 1), 256>>>(h, 256, 0, 0, bhi + OFF_BOT, blo + OFF_BOT, 0,
                                    nullptr, v, 128, 0, 0, NN, 256, 128);
    k_segreduce<128, 32><<<NN, 128>>>(u, v, agg, alpha, beta, avg_log);
    k_wmma<<<dim3(mt, 2, 1), 256>>>(h, 256, 0, 0, bhi + OFF_X, blo + OFF_X, 0,
                                    post2b, px, 128, 0, 0, NN, 256, 128);
    k_wmma<<<dim3(mt, 2, 4), 256>>>(agg, 512, 0, 128, bhi + OFF_CAT, blo + OFF_CAT,
                                    96 * 128, nullptr, pc, 384, 0, 96, NN, 128, 96);
    k_combine<<<(NN * 128 + 255) / 256, 256>>>(px, pc, alpha, beta, post, 128, 32, 384);
    k_wmma<<<dim3(mt, 2, 1), 256>>>(post, 128, 0, 0, bhi + OFF_LIN, blo + OFF_LIN, 0,
                                    lin2b, lin, 128, 0, 0, NN, 128, 128);
    k_zero_f<<<1, 256>>>(bnsum, 256);
    k_zero_f<<<1, 256>>>(bnsq, 256);
    k_bnstats<<<512, 128>>>(lin, bnsum, bnsq, NN, 128);
    k_bnapply<<<(NN * 128 + 255) / 256, 256>>>(lin, bnsum, bnsq, bn2g, bn2b,
                                               (float*)d_out, NN, 128);
}

// round 7
// speedup vs baseline: 2.6127x; 1.4372x over previous
#include <cuda_runtime.h>
#include <cuda_bf16.h>
#include <math.h>
#include <stdint.h>

#define NN 25000
#define EE 400000

// ---------------- device scratch ----------------
__device__ int   g_deg[NN];
__device__ int   g_rowptr[NN + 1];
__device__ int   g_cursor[NN];
__device__ int   g_ssrc[EE];
__device__ float g_uvx[NN * 768];
__device__ float g_pc[NN * 768];
__device__ float g_lin[NN * 256];
__device__ float g_alpha[NN];
__device__ float g_beta[NN];
__device__ float g_bnsum[256];
__device__ float g_bnsq[256];
__device__ __nv_bfloat16 g_xh[NN * 128],   g_xl[NN * 128];
__device__ __nv_bfloat16 g_hh[NN * 256],   g_hl[NN * 256];
__device__ __nv_bfloat16 g_aggh[NN * 1024], g_aggl[NN * 1024];
__device__ __nv_bfloat16 g_posth[NN * 256], g_postl[NN * 256];

// bf16 weight pool (hi/lo), element offsets
#define OFF_UVX 0
#define OFF_CAT 98304
#define OFF_LIN 294912
#define POOL    360448
__device__ __nv_bfloat16 g_ph[POOL];
__device__ __nv_bfloat16 g_pl[POOL];
__device__ float g_bias[1024];   // [0,768): uvx bias; [768,1024): lin bias

__device__ __forceinline__ uint32_t s2u(const void* p) {
    return (uint32_t)__cvta_generic_to_shared(p);
}
__device__ __forceinline__ void bsplit(float v, __nv_bfloat16* oh, __nv_bfloat16* ol) {
    __nv_bfloat16 h = __float2bfloat16(v);
    *oh = h;
    *ol = __float2bfloat16(v - __bfloat162float(h));
}

// ---------------- CSR build ----------------
__global__ void k_zero_int(int* p, int n) {
    int i = blockIdx.x * blockDim.x + threadIdx.x;
    if (i < n) p[i] = 0;
}
__global__ void k_zero_f(float* p, int n) {
    int i = blockIdx.x * blockDim.x + threadIdx.x;
    if (i < n) p[i] = 0.f;
}
__global__ void k_hist(const int* __restrict__ eidx) {
    int e = blockIdx.x * blockDim.x + threadIdx.x;
    if (e < EE) atomicAdd(&g_deg[eidx[EE + e]], 1);
}
__global__ void k_scan() {
    __shared__ int part[1024];
    const int CH = (NN + 1023) / 1024;
    int t = threadIdx.x;
    int base = t * CH;
    int s = 0;
    for (int i = 0; i < CH; i++) {
        int idx = base + i;
        if (idx < NN) s += g_deg[idx];
    }
    part[t] = s;
    __syncthreads();
    for (int off = 1; off < 1024; off <<= 1) {
        int v = 0;
        if (t >= off) v = part[t - off];
        __syncthreads();
        part[t] += v;
        __syncthreads();
    }
    int run = (t == 0) ? 0 : part[t - 1];
    for (int i = 0; i < CH; i++) {
        int idx = base + i;
        if (idx < NN) {
            g_rowptr[idx] = run;
            g_cursor[idx] = run;
            run += g_deg[idx];
        }
    }
    if (t == 1023) g_rowptr[NN] = EE;
}
__global__ void k_scatter(const int* __restrict__ eidx) {
    int e = blockIdx.x * blockDim.x + threadIdx.x;
    if (e < EE) {
        int tgt = eidx[EE + e];
        int pos = atomicAdd(&g_cursor[tgt], 1);
        g_ssrc[pos] = eidx[e];
    }
}

// ---------------- activation split ----------------
__global__ void k_split(const float* __restrict__ in, __nv_bfloat16* __restrict__ oh,
                        __nv_bfloat16* __restrict__ ol, int n) {
    int i = blockIdx.x * blockDim.x + threadIdx.x;
    if (i < n) bsplit(in[i], oh + i, ol + i);
}

// ---------------- weight prep ----------------
__device__ __forceinline__ void put_w(float w, int out_idx) {
    bsplit(w, g_ph + out_idx, g_pl + out_idx);
}
// Merged B layout: UVX rows [top(TF) | bot(TF) | x(TF)], K=Fin.
// CAT rows [t, blk, f] K=TF.  LIN rows linN, K=linK.
__global__ void k_prep(const float* __restrict__ preW, const float* __restrict__ preB,
                       const float* __restrict__ postW, const float* __restrict__ postB,
                       const float* __restrict__ linW, const float* __restrict__ linB,
                       int Fin, int F, int linN, int linK) {
    int TF = 4 * F;
    int KW = Fin + 12 * F;
    int sUVX = 3 * TF * Fin;
    int sCAT = 3 * TF * TF;
    int sLIN = linN * linK;
    int sB = 3 * TF + linN;
    int total = sUVX + sCAT + sLIN + sB;
    for (int i = blockIdx.x * blockDim.x + threadIdx.x; i < total; i += gridDim.x * blockDim.x) {
        if (i < sUVX) {
            int n = i / Fin, k = i % Fin;
            float w;
            if (n < TF) {
                int t = n / F, f = n % F;
                w = preW[(t * 2 * Fin + k) * F + f];
            } else if (n < 2 * TF) {
                int m = n - TF;
                int t = m / F, f = m % F;
                w = preW[(t * 2 * Fin + Fin + k) * F + f];
            } else {
                int m = n - 2 * TF;
                int t = m / F, f = m % F;
                w = postW[(t * KW + k) * F + f];
            }
            put_w(w, OFF_UVX + n * Fin + k);
        } else if (i < sUVX + sCAT) {
            int j = i - sUVX;
            int r = j / TF, k = j % TF;
            int t = r / (3 * F);
            int n2 = r % (3 * F);
            int blk = n2 / F, f = n2 % F;
            put_w(postW[(t * KW + Fin + blk * TF + k) * F + f], OFF_CAT + r * TF + k);
        } else if (i < sUVX + sCAT + sLIN) {
            int j = i - sUVX - sCAT;
            int n = j / linK, k = j % linK;
            put_w(linW[k * linN + n], OFF_LIN + n * linK + k);
        } else {
            int j = i - sUVX - sCAT - sLIN;
            if (j < 3 * TF) {
                float b = (j < TF) ? preB[j] : (j < 2 * TF ? 0.f : postB[j - 2 * TF]);
                g_bias[j] = b;
            } else {
                g_bias[768 + (j - 3 * TF)] = linB[j - 3 * TF];
            }
        }
    }
}

// ---------------- mma helpers ----------------
#define LDMX4(r, addr)                                                              \
    asm volatile("ldmatrix.sync.aligned.m8n8.x4.shared.b16 {%0,%1,%2,%3}, [%4];"    \
                 : "=r"((r)[0]), "=r"((r)[1]), "=r"((r)[2]), "=r"((r)[3])           \
                 : "r"(addr))
__device__ __forceinline__ void mma16816(float* c, const uint32_t* a, const uint32_t* b) {
    asm volatile(
        "mma.sync.aligned.m16n8k16.row.col.f32.bf16.bf16.f32 "
        "{%0,%1,%2,%3}, {%4,%5,%6,%7}, {%8,%9}, {%0,%1,%2,%3};"
        : "+f"(c[0]), "+f"(c[1]), "+f"(c[2]), "+f"(c[3])
        : "r"(a[0]), "r"(a[1]), "r"(a[2]), "r"(a[3]), "r"(b[0]), "r"(b[1]));
}
#define CPA(d, s, pb) \
    asm volatile("cp.async.ca.shared.global [%0], [%1], 16, %2;\n" ::"r"(d), "l"(s), "r"(pb))
#define CP_COMMIT() asm volatile("cp.async.commit_group;\n" ::: "memory")
#define CP_WAIT1() asm volatile("cp.async.wait_group 1;\n" ::: "memory")
#define CP_WAIT0() asm volatile("cp.async.wait_group 0;\n" ::: "memory")

// ---------------- bf16x3 GEMM, double-buffered cp.async ----------------
// C[row, z*cz + col] = sum_k A[z*az + row*lda + k] * B[z][col, k] (+bias[col])
// A: bf16 hi/lo [M, lda]; B: pool hi/lo rows stride K. Tile 128Mx64N, KC=32.
__global__ __launch_bounds__(256, 2) void k_gemm2(
    const __nv_bfloat16* __restrict__ Ah, const __nv_bfloat16* __restrict__ Al,
    int lda, int az,
    const __nv_bfloat16* __restrict__ Bh, const __nv_bfloat16* __restrict__ Bl,
    int bz, int Nz,
    const float* __restrict__ bias, float* __restrict__ C, int ldc, int cz,
    int M, int K) {
    extern __shared__ char smem[];
    const int STG = 30720;  // per stage: Ah 10240 | Al 10240 | Bh 5120 | Bl 5120
    uint32_t sbase = s2u(smem);
    int tid = threadIdx.x;
    int w = tid >> 5, lane = tid & 31;
    int wm = w & 3, wn = w >> 2;
    int bm = blockIdx.x * 128, bn = blockIdx.y * 64;
    int z = blockIdx.z;

    const __nv_bfloat16* A0h = Ah + (size_t)z * az;
    const __nv_bfloat16* A0l = Al + (size_t)z * az;
    const __nv_bfloat16* B0h = Bh + (size_t)z * bz;
    const __nv_bfloat16* B0l = Bl + (size_t)z * bz;

    int arow = tid >> 2, aq = tid & 3;   // A: 2 iterations cover 128 rows
    int brow = tid >> 2, bq = tid & 3;   // B: 64 rows

    auto issue = [&](int i) {
        int s = i & 1;
        uint32_t sb = sbase + s * STG;
        int k0 = i * 32;
#pragma unroll
        for (int r = 0; r < 2; r++) {
            int row = arow + r * 64;
            int rg = bm + row;
            int pb = (rg < M) ? 16 : 0;
            int rc = (rg < M) ? rg : (M - 1);
            const __nv_bfloat16* sh = A0h + (size_t)rc * lda + k0 + aq * 8;
            const __nv_bfloat16* sl = A0l + (size_t)rc * lda + k0 + aq * 8;
            uint32_t d = sb + row * 80 + aq * 16;
            CPA(d, sh, pb);
            CPA(d + 10240, sl, pb);
        }
        {
            int rg = bn + brow;
            int pb = (rg < Nz) ? 16 : 0;
            int rc = (rg < Nz) ? rg : (Nz - 1);
            const __nv_bfloat16* sh = B0h + (size_t)rc * K + k0 + bq * 8;
            const __nv_bfloat16* sl = B0l + (size_t)rc * K + k0 + bq * 8;
            uint32_t d = sb + 20480 + brow * 80 + bq * 16;
            CPA(d, sh, pb);
            CPA(d + 5120, sl, pb);
        }
        CP_COMMIT();
    };

    float acc[2][4][4] = {};
    int nch = K / 32;
    issue(0);
    for (int i = 0; i < nch; i++) {
        if (i + 1 < nch) {
            issue(i + 1);
            CP_WAIT1();
        } else {
            CP_WAIT0();
        }
        __syncthreads();
        uint32_t sb = sbase + (i & 1) * STG;
#pragma unroll
        for (int ks = 0; ks < 2; ks++) {
            uint32_t ah[2][4], al[2][4], bh[4][2], bl[4][2];
#pragma unroll
            for (int mi = 0; mi < 2; mi++) {
                int r = wm * 32 + mi * 16 + (lane & 15);
                int kk = ks * 16 + ((lane >> 4) << 3);
                uint32_t ad = sb + r * 80 + kk * 2;
                LDMX4(ah[mi], ad);
                LDMX4(al[mi], ad + 10240);
            }
#pragma unroll
            for (int np = 0; np < 2; np++) {
                int rr = wn * 32 + np * 16 + (lane & 7) + ((lane & 16) ? 8 : 0);
                int kk = ks * 16 + ((lane & 8) ? 8 : 0);
                uint32_t bd = sb + 20480 + rr * 80 + kk * 2;
                uint32_t t[4];
                LDMX4(t, bd);
                bh[np * 2][0] = t[0]; bh[np * 2][1] = t[1];
                bh[np * 2 + 1][0] = t[2]; bh[np * 2 + 1][1] = t[3];
                LDMX4(t, bd + 5120);
                bl[np * 2][0] = t[0]; bl[np * 2][1] = t[1];
                bl[np * 2 + 1][0] = t[2]; bl[np * 2 + 1][1] = t[3];
            }
#pragma unroll
            for (int mi = 0; mi < 2; mi++)
#pragma unroll
                for (int ni = 0; ni < 4; ni++) {
                    mma16816(acc[mi][ni], ah[mi], bh[ni]);
                    mma16816(acc[mi][ni], ah[mi], bl[ni]);
                    mma16816(acc[mi][ni], al[mi], bh[ni]);
                }
        }
        __syncthreads();
    }

    // epilogue
#pragma unroll
    for (int mi = 0; mi < 2; mi++) {
#pragma unroll
        for (int ni = 0; ni < 4; ni++) {
            int col = bn + wn * 32 + ni * 8 + 2 * (lane & 3);
            if (col >= Nz) continue;
            float bv0 = bias ? bias[col] : 0.f;
            float bv1 = bias ? bias[col + 1] : 0.f;
            int r0 = bm + wm * 32 + mi * 16 + (lane >> 2);
            size_t cb = (size_t)z * cz + col;
            if (r0 < M) {
                float2 o = make_float2(acc[mi][ni][0] + bv0, acc[mi][ni][1] + bv1);
                *(float2*)(C + (size_t)r0 * ldc + cb) = o;
            }
            if (r0 + 8 < M) {
                float2 o = make_float2(acc[mi][ni][2] + bv0, acc[mi][ni][3] + bv1);
                *(float2*)(C + (size_t)(r0 + 8) * ldc + cb) = o;
            }
        }
    }
}

// ---------------- segment reduce (writes agg directly as bf16 hi/lo) ----------------
template <int C, int F>
__global__ void k_segreduce(const float* __restrict__ uvx, int ld, int voff,
                            __nv_bfloat16* __restrict__ aggh, __nv_bfloat16* __restrict__ aggl,
                            float* __restrict__ alpha, float* __restrict__ beta,
                            const float* __restrict__ avg_log) {
    int n = blockIdx.x;
    int j = threadIdx.x;
    int beg = g_rowptr[n], end = g_rowptr[n + 1];
    float s = 0.f, s2 = 0.f, mn = 3.4e38f, mx = -3.4e38f;
    for (int e = beg; e < end; e++) {
        int sidx = g_ssrc[e];
        float val = uvx[(size_t)sidx * ld + voff + j];
        s += val;
        s2 += val * val;
        mn = fminf(mn, val);
        mx = fmaxf(mx, val);
    }
    int deg = end - beg;
    float uu = uvx[(size_t)n * ld + j];
    float degf = (float)deg;
    float degc = fmaxf(degf, 1.f);
    float mean = (deg > 0) ? (uu + s / degf) : 0.f;
    float s2f = degf * uu * uu + 2.f * uu * s + s2;
    float var = fmaxf(s2f / degc - mean * mean, 0.f);
    float sd = sqrtf(var + 1e-5f);
    float mnv = (deg > 0) ? (uu + mn) : 0.f;
    float mxv = (deg > 0) ? (uu + mx) : 0.f;
    int t = j / F, f = j % F;
    size_t base = (size_t)n * (4 * C) + t * (4 * F);
    bsplit(mean, aggh + base + f, aggl + base + f);
    bsplit(mnv, aggh + base + F + f, aggl + base + F + f);
    bsplit(mxv, aggh + base + 2 * F + f, aggl + base + 2 * F + f);
    bsplit(sd, aggh + base + 3 * F + f, aggl + base + 3 * F + f);
    if (j == 0) {
        float dl = logf(degc + 1.f);
        alpha[n] = dl / avg_log[0];
        beta[n] = avg_log[0] / dl;
    }
}

// ---------------- combine: post = px + p1 + a*p2 + b*p3 -> bf16 hi/lo ----------------
__global__ void k_combine(const float* __restrict__ uvx, int ld, int pxoff,
                          const float* __restrict__ pc, int ldpc,
                          const float* __restrict__ alpha, const float* __restrict__ beta,
                          __nv_bfloat16* __restrict__ oh, __nv_bfloat16* __restrict__ ol,
                          int C, int F) {
    int idx = blockIdx.x * blockDim.x + threadIdx.x;
    if (idx < NN * C) {
        int n = idx / C, c = idx % C;
        int t = c / F, f = c % F;
        const float* p = pc + (size_t)n * ldpc + t * 3 * F;
        float v = uvx[(size_t)n * ld + pxoff + c] + p[f] + alpha[n] * p[F + f] +
                  beta[n] * p[2 * F + f];
        bsplit(v, oh + idx, ol + idx);
    }
}

// ---------------- batchnorm ----------------
__global__ void k_bnstats(const float* __restrict__ Y, float* __restrict__ sum,
                          float* __restrict__ sq, int M, int C) {
    int j = threadIdx.x;
    if (j >= C) return;
    float s = 0.f, q = 0.f;
    for (int r = blockIdx.x; r < M; r += gridDim.x) {
        float v = Y[(size_t)r * C + j];
        if (!isfinite(v)) v = 0.f;
        s += v;
        q += v * v;
    }
    atomicAdd(&sum[j], s);
    atomicAdd(&sq[j], q);
}
// relu(bn) -> bf16 hi/lo
__global__ void k_bnapply_split(const float* __restrict__ Y, const float* __restrict__ sum,
                                const float* __restrict__ sq, const float* __restrict__ g,
                                const float* __restrict__ b, __nv_bfloat16* __restrict__ oh,
                                __nv_bfloat16* __restrict__ ol, int M, int C) {
    int idx = blockIdx.x * blockDim.x + threadIdx.x;
    if (idx < M * C) {
        int j = idx % C;
        float m = sum[j] / (float)M;
        float var = sq[j] / (float)M - m * m;
        float inv = rsqrtf(var + 1e-5f);
        float y = Y[idx];
        if (!isfinite(y)) y = 0.f;
        float o = fmaxf(0.f, g[j] * (y - m) * inv + b[j]);
        bsplit(o, oh + idx, ol + idx);
    }
}
// relu(bn) -> fp32 (final output)
__global__ void k_bnapply_out(const float* __restrict__ Y, const float* __restrict__ sum,
                              const float* __restrict__ sq, const float* __restrict__ g,
                              const float* __restrict__ b, float* __restrict__ OUT, int M,
                              int C) {
    int idx = blockIdx.x * blockDim.x + threadIdx.x;
    if (idx < M * C) {
        int j = idx % C;
        float m = sum[j] / (float)M;
        float var = sq[j] / (float)M - m * m;
        float inv = rsqrtf(var + 1e-5f);
        float y = Y[idx];
        if (!isfinite(y)) y = 0.f;
        OUT[idx] = fmaxf(0.f, g[j] * (y - m) * inv + b[j]);
    }
}

// ---------------- launch ----------------
extern "C" void kernel_launch(void* const* d_in, const int* in_sizes, int n_in,
                              void* d_out, int out_size) {
    const float* x       = (const float*)d_in[0];
    const int*   eidx    = (const int*)d_in[1];
    const float* avg_log = (const float*)d_in[2];
    const float* pre1W   = (const float*)d_in[3];
    const float* pre1b   = (const float*)d_in[4];
    const float* post1W  = (const float*)d_in[5];
    const float* post1b  = (const float*)d_in[6];
    const float* lin1W   = (const float*)d_in[7];
    const float* lin1b   = (const float*)d_in[8];
    const float* bn1g    = (const float*)d_in[9];
    const float* bn1b    = (const float*)d_in[10];
    const float* pre2W   = (const float*)d_in[11];
    const float* pre2b   = (const float*)d_in[12];
    const float* post2W  = (const float*)d_in[13];
    const float* post2b  = (const float*)d_in[14];
    const float* lin2W   = (const float*)d_in[15];
    const float* lin2b   = (const float*)d_in[16];
    const float* bn2g    = (const float*)d_in[17];
    const float* bn2b    = (const float*)d_in[18];

    int* deg;
    float *uvx, *pc, *lin, *alpha, *beta, *bnsum, *bnsq, *bias;
    __nv_bfloat16 *xh, *xl, *hh, *hl, *aggh, *aggl, *posth, *postl, *ph, *pl;
    cudaGetSymbolAddress((void**)&deg, g_deg);
    cudaGetSymbolAddress((void**)&uvx, g_uvx);
    cudaGetSymbolAddress((void**)&pc, g_pc);
    cudaGetSymbolAddress((void**)&lin, g_lin);
    cudaGetSymbolAddress((void**)&alpha, g_alpha);
    cudaGetSymbolAddress((void**)&beta, g_beta);
    cudaGetSymbolAddress((void**)&bnsum, g_bnsum);
    cudaGetSymbolAddress((void**)&bnsq, g_bnsq);
    cudaGetSymbolAddress((void**)&bias, g_bias);
    cudaGetSymbolAddress((void**)&xh, g_xh);
    cudaGetSymbolAddress((void**)&xl, g_xl);
    cudaGetSymbolAddress((void**)&hh, g_hh);
    cudaGetSymbolAddress((void**)&hl, g_hl);
    cudaGetSymbolAddress((void**)&aggh, g_aggh);
    cudaGetSymbolAddress((void**)&aggl, g_aggl);
    cudaGetSymbolAddress((void**)&posth, g_posth);
    cudaGetSymbolAddress((void**)&postl, g_postl);
    cudaGetSymbolAddress((void**)&ph, g_ph);
    cudaGetSymbolAddress((void**)&pl, g_pl);

    const int SMEM = 61440;
    cudaFuncSetAttribute(k_gemm2, cudaFuncAttributeMaxDynamicSharedMemorySize, SMEM);

    // ---- CSR build ----
    k_zero_int<<<(NN + 255) / 256, 256>>>(deg, NN);
    k_hist<<<(EE + 255) / 256, 256>>>(eidx);
    k_scan<<<1, 1024>>>();
    k_scatter<<<(EE + 255) / 256, 256>>>(eidx);

    const int mt = (NN + 127) / 128;  // 196

    // =================== layer 1 (Fin=128, F=64, TF=256) ===================
    k_prep<<<512, 256>>>(pre1W, pre1b, post1W, post1b, lin1W, lin1b, 128, 64, 256, 256);
    k_split<<<(NN * 128 + 255) / 256, 256>>>(x, xh, xl, NN * 128);
    // merged u|v|px : [NN,768] = x @ B_uvx
    k_gemm2<<<dim3(mt, 12, 1), 256, SMEM>>>(xh, xl, 128, 0, ph + OFF_UVX, pl + OFF_UVX,
                                            0, 768, bias, uvx, 768, 0, NN, 128);
    k_segreduce<256, 64><<<NN, 256>>>(uvx, 768, 256, aggh, aggl, alpha, beta, avg_log);
    // cat: per-tower agg @ [W1|W2|W3]
    k_gemm2<<<dim3(mt, 3, 4), 256, SMEM>>>(aggh, aggl, 1024, 256, ph + OFF_CAT, pl + OFF_CAT,
                                           192 * 256, 192, nullptr, pc, 768, 192, NN, 256);
    k_combine<<<(NN * 256 + 255) / 256, 256>>>(uvx, 768, 512, pc, 768, alpha, beta,
                                               posth, postl, 256, 64);
    k_gemm2<<<dim3(mt, 4, 1), 256, SMEM>>>(posth, postl, 256, 0, ph + OFF_LIN, pl + OFF_LIN,
                                           0, 256, bias + 768, lin, 256, 0, NN, 256);
    k_zero_f<<<1, 256>>>(bnsum, 256);
    k_zero_f<<<1, 256>>>(bnsq, 256);
    k_bnstats<<<512, 256>>>(lin, bnsum, bnsq, NN, 256);
    k_bnapply_split<<<(NN * 256 + 255) / 256, 256>>>(lin, bnsum, bnsq, bn1g, bn1b, hh, hl,
                                                     NN, 256);

    // =================== layer 2 (Fin=256, F=32, TF=128) ===================
    k_prep<<<512, 256>>>(pre2W, pre2b, post2W, post2b, lin2W, lin2b, 256, 32, 128, 128);
    k_gemm2<<<dim3(mt, 6, 1), 256, SMEM>>>(hh, hl, 256, 0, ph + OFF_UVX, pl + OFF_UVX,
                                           0, 384, bias, uvx, 384, 0, NN, 256);
    k_segreduce<128, 32><<<NN, 128>>>(uvx, 384, 128, aggh, aggl, alpha, beta, avg_log);
    k_gemm2<<<dim3(mt, 2, 4), 256, SMEM>>>(aggh, aggl, 512, 128, ph + OFF_CAT, pl + OFF_CAT,
                                           96 * 128, 96, nullptr, pc, 384, 96, NN, 128);
    k_combine<<<(NN * 128 + 255) / 256, 256>>>(uvx, 384, 256, pc, 384, alpha, beta,
                                               posth, postl, 128, 32);
    k_gemm2<<<dim3(mt, 2, 1), 256, SMEM>>>(posth, postl, 128, 0, ph + OFF_LIN, pl + OFF_LIN,
                                           0, 128, bias + 768, lin, 128, 0, NN, 128);
    k_zero_f<<<1, 256>>>(bnsum, 256);
    k_zero_f<<<1, 256>>>(bnsq, 256);
    k_bnstats<<<512, 128>>>(lin, bnsum, bnsq, NN, 128);
    k_bnapply_out<<<(NN * 128 + 255) / 256, 256>>>(lin, bnsum, bnsq, bn2g, bn2b,
                                                   (float*)d_out, NN, 128);
}